// round 1
// baseline (speedup 1.0000x reference)
#include <cuda_runtime.h>

// Batched 2nd-order IIR: y[t] = b0*u[t] + b1*u[t-1] - a1*y[t-1] - a2*y[t-2]
// Parallelized via chunked superposition: per-chunk zero-state response +
// homogeneous-response correction, with a tiny per-row affine scan over chunks.

#define LCH      64     // chunk length (timesteps per thread)
#define NTHREADS 256    // threads per CTA == chunks per row (T = 16384)

__global__ __launch_bounds__(NTHREADS, 1)
void iir_chunked_kernel(const float* __restrict__ bco,
                        const float* __restrict__ aco,
                        const float* __restrict__ u,
                        const float* __restrict__ yinit,
                        const float* __restrict__ uinit,
                        float* __restrict__ yout,
                        int T)
{
    extern __shared__ float smem[];
    const int C    = T / LCH;           // chunks per row (256)
    const int SUSZ = C * (LCH + 1);     // padded data region (stride 65 -> conflict-free)
    float* su    = smem;                // [C * 65]  u, then in-place zero-state y0
    float* alpha = su + SUSZ;           // [LCH] homogeneous response to y[-1]=1
    float* beta  = alpha + LCH;         // [LCH] homogeneous response to y[-2]=1
    float* s1    = beta + LCH;          // [C] scanned state y[-1] entering each chunk
    float* s2    = s1 + C;              // [C] scanned state y[-2] entering each chunk

    const int row = blockIdx.x;
    const int tid = threadIdx.x;

    const float b0 = bco[0], b1 = bco[1];
    const float a1 = aco[0], a2 = aco[1];

    const float* urow = u + (size_t)row * T;

    // ---- Phase 0: coalesced GMEM -> padded SMEM ----
    for (int i = tid; i < T; i += NTHREADS) {
        su[(i >> 6) * (LCH + 1) + (i & 63)] = urow[i];
    }

    // Homogeneous impulse responses (one thread; 64 short steps).
    // alpha: x=0, y[-1]=1, y[-2]=0.  beta: x=0, y[-1]=0, y[-2]=1.
    if (tid == 0) {
        float p1 = 1.f, p2 = 0.f;   // alpha state
        float q1 = 0.f, q2 = 1.f;   // beta state
        #pragma unroll 4
        for (int t = 0; t < LCH; t++) {
            float pa = -a1 * p1 - a2 * p2;
            float qb = -a1 * q1 - a2 * q2;
            alpha[t] = pa; beta[t] = qb;
            p2 = p1; p1 = pa;
            q2 = q1; q1 = qb;
        }
    }
    __syncthreads();

    // ---- Phase 1 prologue: read cross-chunk boundary u BEFORE in-place overwrite ----
    const int base = tid * (LCH + 1);
    float uprev = 0.f;
    if (tid < C) {
        // global index tid*64 - 1 lives at shared slot (tid-1)*65 + 63 = base - 2
        uprev = (tid == 0) ? uinit[2 * row] : su[base - 2];
    }
    __syncthreads();

    // ---- Phase 1: zero-state response per chunk, in place ----
    if (tid < C) {
        float yp1 = 0.f, yp2 = 0.f;
        #pragma unroll 8
        for (int t = 0; t < LCH; t++) {
            float uc = su[base + t];
            float x  = b0 * uc + b1 * uprev;
            float yt = x - a1 * yp1 - a2 * yp2;
            su[base + t] = yt;
            uprev = uc;
            yp2 = yp1; yp1 = yt;
        }
    }
    __syncthreads();

    // ---- Phase 2: serial affine scan over chunk states (one thread, C steps) ----
    // state entering chunk c+1 = d_c + A * state_c, A fixed 2x2 from alpha/beta tails.
    if (tid == 0) {
        const float A11 = alpha[LCH - 1], A12 = beta[LCH - 1];
        const float A21 = alpha[LCH - 2], A22 = beta[LCH - 2];
        float c1 = yinit[2 * row];       // y[-1]
        float c2 = yinit[2 * row + 1];   // y[-2]
        for (int c = 0; c < C; c++) {
            s1[c] = c1; s2[c] = c2;
            const int bb = c * (LCH + 1);
            float d1 = su[bb + LCH - 1];
            float d2 = su[bb + LCH - 2];
            float n1 = d1 + A11 * c1 + A12 * c2;
            float n2 = d2 + A21 * c1 + A22 * c2;
            c1 = n1; c2 = n2;
        }
    }
    __syncthreads();

    // ---- Phase 3: superposition fixup + coalesced write ----
    float* yrow = yout + (size_t)row * T;
    for (int i = tid; i < T; i += NTHREADS) {
        int ch  = i >> 6;
        int off = i & 63;
        yrow[i] = su[ch * (LCH + 1) + off] + alpha[off] * s1[ch] + beta[off] * s2[ch];
    }
}

extern "C" void kernel_launch(void* const* d_in, const int* in_sizes, int n_in,
                              void* d_out, int out_size) {
    const float* bco   = (const float*)d_in[0];  // (n_b)
    const float* aco   = (const float*)d_in[1];  // (n_a)
    const float* u     = (const float*)d_in[2];  // (B, T)
    const float* yinit = (const float*)d_in[3];  // (B, 2)
    const float* uinit = (const float*)d_in[4];  // (B, 2)
    float* yout        = (float*)d_out;          // (B, T)

    const int B = in_sizes[3] / 2;               // y_init is (B, 2)
    const int T = in_sizes[2] / B;               // u_in is (B, T)
    const int C = T / LCH;

    // smem: padded data (T + C) + alpha/beta (2*LCH) + scan states (2*C)
    size_t smem_bytes = (size_t)(T + C + 2 * LCH + 2 * C) * sizeof(float);
    cudaFuncSetAttribute(iir_chunked_kernel,
                         cudaFuncAttributeMaxDynamicSharedMemorySize,
                         (int)smem_bytes);

    iir_chunked_kernel<<<B, NTHREADS, smem_bytes>>>(bco, aco, u, yinit, uinit, yout, T);
}

// round 4
// speedup vs baseline: 1.7732x; 1.7732x over previous
#include <cuda_runtime.h>

// Batched 2nd-order IIR via chunked superposition, segmented for occupancy:
//   - row processed as NSEG sequential segments of SEG samples (carry state across)
//   - per segment: 256 threads x 16-step zero-state recurrences
//   - chunk boundary states resolved by a Kogge-Stone affine scan (8 levels)
//   - superposition fixup fused into the coalesced store

#define LCH      16                 // chunk length per thread
#define SEG      4096               // samples per segment
#define CPS      (SEG / LCH)        // 256 chunks per segment == NTHREADS
#define NTHREADS 256
#define STRIDE   (LCH + 1)          // 17 -> conflict-free per-chunk smem rows
#define NLEV     8                  // log2(CPS)

__global__ __launch_bounds__(NTHREADS, 8)
void iir_seg_kernel(const float* __restrict__ bco,
                    const float* __restrict__ aco,
                    const float* __restrict__ u,
                    const float* __restrict__ yinit,
                    const float* __restrict__ uinit,
                    float* __restrict__ yout,
                    int T)
{
    __shared__ float su[CPS * STRIDE];        // 17408 B: u, then in-place y0
    __shared__ float buf1[2][CPS];            // scan exchange (comp 1)
    __shared__ float buf2[2][CPS];            // scan exchange (comp 2)
    __shared__ float alpha[LCH], beta[LCH];   // homogeneous responses
    __shared__ float pw[NLEV][4];             // A^(2^k), row-major 2x2
    __shared__ float carry[3];                // y[-1], y[-2], u[-1] across segments

    const int row = blockIdx.x;
    const int tid = threadIdx.x;

    const float b0 = bco[0], b1 = bco[1];
    const float a1 = aco[0], a2 = aco[1];

    const float* urow = u + (size_t)row * T;
    float*       yrow = yout + (size_t)row * T;

    // ---- One-time per CTA: alpha/beta, matrix powers, initial carry ----
    if (tid == 0) {
        float p1 = 1.f, p2 = 0.f;   // response to y[-1]=1
        float q1 = 0.f, q2 = 1.f;   // response to y[-2]=1
        #pragma unroll
        for (int t = 0; t < LCH; t++) {
            float pa = -a1 * p1 - a2 * p2;
            float qb = -a1 * q1 - a2 * q2;
            alpha[t] = pa; beta[t] = qb;
            p2 = p1; p1 = pa;
            q2 = q1; q1 = qb;
        }
        // A = [[alpha[L-1], beta[L-1]], [alpha[L-2], beta[L-2]]]
        float w11 = p1, w12 = q1, w21 = p2, w22 = q2;
        #pragma unroll
        for (int k = 0; k < NLEV; k++) {
            pw[k][0] = w11; pw[k][1] = w12; pw[k][2] = w21; pw[k][3] = w22;
            float n11 = w11 * w11 + w12 * w21;
            float n12 = w11 * w12 + w12 * w22;
            float n21 = w21 * w11 + w22 * w21;
            float n22 = w21 * w12 + w22 * w22;
            w11 = n11; w12 = n12; w21 = n21; w22 = n22;
        }
        carry[0] = yinit[2 * row];       // y[-1]
        carry[1] = yinit[2 * row + 1];   // y[-2]
        carry[2] = uinit[2 * row];       // u[-1]
    }
    __syncthreads();

    const int base = tid * STRIDE;
    const int nseg = T / SEG;

    for (int g = 0; g < nseg; g++) {
        const float* useg = urow + g * SEG;

        // ---- load segment (coalesced GMEM -> padded SMEM) ----
        #pragma unroll 4
        for (int k = 0; k < SEG / NTHREADS; k++) {
            int i = tid + k * NTHREADS;
            su[(i >> 4) * STRIDE + (i & 15)] = useg[i];
        }
        __syncthreads();

        // boundary u for each chunk, read BEFORE in-place overwrite
        float uprev = (tid == 0) ? carry[2] : su[base - 2];  // (tid-1)*17+15
        __syncthreads();

        // ---- zero-state response per chunk, in place ----
        float yp1 = 0.f, yp2 = 0.f;
        #pragma unroll
        for (int t = 0; t < LCH; t++) {
            float uc = su[base + t];
            float x  = b0 * uc + b1 * uprev;
            float yt = x - a1 * yp1 - a2 * yp2;
            su[base + t] = yt;
            uprev = uc;
            yp2 = yp1; yp1 = yt;
        }
        if (tid == NTHREADS - 1) carry[2] = uprev;  // last u of segment
        __syncthreads();

        // ---- Kogge-Stone affine scan over chunk states ----
        // element e_c: c==0 -> segment entry state; else d_{c-1} (zero-state tail)
        float rs1, rs2;
        if (tid == 0) { rs1 = carry[0]; rs2 = carry[1]; }
        else          { rs1 = su[base - 2]; rs2 = su[base - 3]; }

        int p = 0;
        #pragma unroll
        for (int k = 0; k < NLEV; k++) {
            buf1[p][tid] = rs1;
            buf2[p][tid] = rs2;
            __syncthreads();
            int off = 1 << k;
            if (tid >= off) {
                float g1 = buf1[p][tid - off];
                float g2 = buf2[p][tid - off];
                rs1 += pw[k][0] * g1 + pw[k][1] * g2;
                rs2 += pw[k][2] * g1 + pw[k][3] * g2;
            }
            p ^= 1;
        }
        // rs = state entering chunk tid; publish for the fixup pass
        buf1[p][tid] = rs1;
        buf2[p][tid] = rs2;
        if (tid == NTHREADS - 1) {
            // segment exit state = actual y at last two samples
            carry[0] = yp1 + pw[0][0] * rs1 + pw[0][1] * rs2;
            carry[1] = yp2 + pw[0][2] * rs1 + pw[0][3] * rs2;
        }
        __syncthreads();

        // ---- superposition fixup fused into coalesced store ----
        float* yseg = yrow + g * SEG;
        #pragma unroll 4
        for (int k = 0; k < SEG / NTHREADS; k++) {
            int i   = tid + k * NTHREADS;
            int ch  = i >> 4;
            int off = i & 15;
            yseg[i] = su[ch * STRIDE + off]
                    + alpha[off] * buf1[p][ch]
                    + beta[off]  * buf2[p][ch];
        }
        __syncthreads();   // su/carry reused next segment
    }
}

extern "C" void kernel_launch(void* const* d_in, const int* in_sizes, int n_in,
                              void* d_out, int out_size) {
    const float* bco   = (const float*)d_in[0];  // (n_b)
    const float* aco   = (const float*)d_in[1];  // (n_a)
    const float* u     = (const float*)d_in[2];  // (B, T)
    const float* yinit = (const float*)d_in[3];  // (B, 2)
    const float* uinit = (const float*)d_in[4];  // (B, 2)
    float* yout        = (float*)d_out;          // (B, T)

    const int B = in_sizes[3] / 2;               // y_init is (B, 2)
    const int T = in_sizes[2] / B;               // u_in is (B, T)

    iir_seg_kernel<<<B, NTHREADS>>>(bco, aco, u, yinit, uinit, yout, T);
}

// round 5
// speedup vs baseline: 2.0984x; 1.1834x over previous
#include <cuda_runtime.h>

// Batched 2nd-order IIR via chunked superposition, float4-vectorized, with a
// register/shuffle affine scan (uniform per-chunk 2x2 matrix M = A^LCH).
//
//   y[t] = b0*u[t] + b1*u[t-1] - a1*y[t-1] - a2*y[t-2]
//
// Per segment (SEG=4096): 256 threads x 16-sample chunks.
//   A: coalesced float4 load -> transposed smem (stride 20, 16B aligned)
//   B: zero-state recurrence per chunk (float4 LDS, conflict-free), y0 in place
//   C: scan of chunk tail-states: 5 shfl levels intra-warp + 8-wide cross-warp
//   D: fixup y = y0 + alpha*s1 + beta*s2 fused into coalesced float4 store

#define LCH      16
#define NTHREADS 256
#define SEG      (NTHREADS * LCH)     // 4096
#define CPS      NTHREADS             // chunks per segment
#define F4PC     5                    // float4 per chunk row (20 floats, padded)
#define NWARP    (NTHREADS / 32)

__global__ __launch_bounds__(NTHREADS, 8)
void iir_shfl_kernel(const float* __restrict__ bco,
                     const float* __restrict__ aco,
                     const float* __restrict__ u,
                     const float* __restrict__ yinit,
                     const float* __restrict__ uinit,
                     float* __restrict__ yout,
                     int T)
{
    __shared__ float4 su4[CPS * F4PC];     // 20 KB: u, then in-place y0
    __shared__ float4 alpha4[4], beta4[4]; // homogeneous responses (16 each)
    __shared__ float  pw[8][4];            // M^(2^k), row-major 2x2
    __shared__ float4 Ltab[32];            // M^(l+1): (m11,m12,m21,m22)
    __shared__ float  agg1[NWARP], agg2[NWARP];
    __shared__ float  q1s[NWARP],  q2s[NWARP];
    __shared__ float  s1[CPS], s2[CPS];    // entering state per chunk
    __shared__ float  carry1, carry2;      // y-state across segments

    float* su = (float*)su4;

    const int row  = blockIdx.x;
    const int tid  = threadIdx.x;
    const int lane = tid & 31;
    const int wid  = tid >> 5;

    const float b0 = bco[0], b1 = bco[1];
    const float a1 = aco[0], a2 = aco[1];

    const float* urow = u + (size_t)row * T;
    float*       yrow = yout + (size_t)row * T;

    // ---- One-time tables (tid 0; other warps proceed to phase A) ----
    if (tid == 0) {
        float* af = (float*)alpha4;
        float* bf = (float*)beta4;
        float p1 = 1.f, p2 = 0.f;   // response to y[-1]=1
        float q1 = 0.f, q2 = 1.f;   // response to y[-2]=1
        #pragma unroll
        for (int t = 0; t < LCH; t++) {
            float pa = -a1 * p1 - a2 * p2;
            float qb = -a1 * q1 - a2 * q2;
            af[t] = pa; bf[t] = qb;
            p2 = p1; p1 = pa;
            q2 = q1; q1 = qb;
        }
        // M = [[alpha15, beta15], [alpha14, beta14]]
        const float M11 = p1, M12 = q1, M21 = p2, M22 = q2;
        float w11 = M11, w12 = M12, w21 = M21, w22 = M22;
        #pragma unroll
        for (int k = 0; k < 8; k++) {
            pw[k][0] = w11; pw[k][1] = w12; pw[k][2] = w21; pw[k][3] = w22;
            float n11 = w11 * w11 + w12 * w21;
            float n12 = w11 * w12 + w12 * w22;
            float n21 = w21 * w11 + w22 * w21;
            float n22 = w21 * w12 + w22 * w22;
            w11 = n11; w12 = n12; w21 = n21; w22 = n22;
        }
        // Ltab[l] = M^(l+1)
        float c11 = M11, c12 = M12, c21 = M21, c22 = M22;
        Ltab[0] = make_float4(c11, c12, c21, c22);
        for (int l = 1; l < 32; l++) {
            float n11 = M11 * c11 + M12 * c21;
            float n12 = M11 * c12 + M12 * c22;
            float n21 = M21 * c11 + M22 * c21;
            float n22 = M21 * c12 + M22 * c22;
            c11 = n11; c12 = n12; c21 = n21; c22 = n22;
            Ltab[l] = make_float4(c11, c12, c21, c22);
        }
        carry1 = yinit[2 * row];       // y[-1]
        carry2 = yinit[2 * row + 1];   // y[-2]
    }

    const int nseg = T / SEG;

    for (int g = 0; g < nseg; g++) {
        const float4* useg4 = (const float4*)(urow + (size_t)g * SEG);

        // ---- Phase A: coalesced load -> transposed padded smem ----
        #pragma unroll
        for (int k = 0; k < 4; k++) {
            int v = tid + k * NTHREADS;
            float4 f = useg4[v];
            su4[(v >> 2) * F4PC + (v & 3)] = f;
        }
        __syncthreads();

        // boundary u (read neighbor's slot BEFORE in-place overwrite)
        float uprev;
        if (tid == 0)
            uprev = (g == 0) ? uinit[2 * row] : urow[(size_t)g * SEG - 1];
        else
            uprev = su[tid * (4 * F4PC) - 5];   // (tid-1)*20 + 15
        __syncthreads();

        // ---- Phase B: zero-state recurrence, y0 in place ----
        float yp1 = 0.f, yp2 = 0.f;
        {
            const int cb = tid * F4PC;
            #pragma unroll
            for (int j = 0; j < 4; j++) {
                float4 f = su4[cb + j];
                float o0 = b0 * f.x + b1 * uprev - a1 * yp1 - a2 * yp2;
                float o1 = b0 * f.y + b1 * f.x   - a1 * o0  - a2 * yp1;
                float o2 = b0 * f.z + b1 * f.y   - a1 * o1  - a2 * o0;
                float o3 = b0 * f.w + b1 * f.z   - a1 * o2  - a2 * o1;
                uprev = f.w; yp1 = o3; yp2 = o2;
                su4[cb + j] = make_float4(o0, o1, o2, o3);
            }
        }

        // ---- Phase C: affine scan over chunk tail states ----
        float rs1 = yp1, rs2 = yp2;          // d_c
        if (tid == 0) {                       // fold segment entry state into e_0
            float c1 = carry1, c2 = carry2;
            rs1 += pw[0][0] * c1 + pw[0][1] * c2;
            rs2 += pw[0][2] * c1 + pw[0][3] * c2;
            s1[0] = c1; s2[0] = c2;           // entering state of chunk 0
        }
        #pragma unroll
        for (int k = 0; k < 5; k++) {
            int sh = 1 << k;
            float g1 = __shfl_up_sync(0xffffffffu, rs1, sh);
            float g2 = __shfl_up_sync(0xffffffffu, rs2, sh);
            float m11 = pw[k][0], m12 = pw[k][1];
            float m21 = pw[k][2], m22 = pw[k][3];
            if (lane >= sh) {
                rs1 += m11 * g1 + m12 * g2;
                rs2 += m21 * g1 + m22 * g2;
            }
        }
        if (lane == 31) { agg1[wid] = rs1; agg2[wid] = rs2; }
        __syncthreads();

        if (wid == 0) {                       // scan 8 warp aggregates (M^32 steps)
            float q1 = 0.f, q2 = 0.f;
            if (lane < NWARP) { q1 = agg1[lane]; q2 = agg2[lane]; }
            #pragma unroll
            for (int k = 0; k < 3; k++) {
                int sh = 1 << k;
                float g1 = __shfl_up_sync(0xffffffffu, q1, sh);
                float g2 = __shfl_up_sync(0xffffffffu, q2, sh);
                float m11 = pw[5 + k][0], m12 = pw[5 + k][1];
                float m21 = pw[5 + k][2], m22 = pw[5 + k][3];
                if (lane >= sh && lane < NWARP) {
                    q1 += m11 * g1 + m12 * g2;
                    q2 += m21 * g1 + m22 * g2;
                }
            }
            if (lane < NWARP) { q1s[lane] = q1; q2s[lane] = q2; }
        }
        __syncthreads();

        if (wid > 0) {                        // splice preceding warps' prefix
            float Q1 = q1s[wid - 1], Q2 = q2s[wid - 1];
            float4 Lm = Ltab[lane];
            rs1 += Lm.x * Q1 + Lm.y * Q2;
            rs2 += Lm.z * Q1 + Lm.w * Q2;
        }
        // rs = state AFTER chunk tid = entering state of chunk tid+1
        if (tid < CPS - 1) { s1[tid + 1] = rs1; s2[tid + 1] = rs2; }
        else               { carry1 = rs1; carry2 = rs2; }
        __syncthreads();

        // ---- Phase D: superposition fixup fused into coalesced store ----
        float4* yseg4 = (float4*)(yrow + (size_t)g * SEG);
        #pragma unroll
        for (int k = 0; k < 4; k++) {
            int v = tid + k * NTHREADS;
            int c = v >> 2, q = v & 3;
            float4 y0 = su4[c * F4PC + q];
            float4 al = alpha4[q];
            float4 be = beta4[q];
            float S1 = s1[c], S2 = s2[c];
            float4 o;
            o.x = y0.x + al.x * S1 + be.x * S2;
            o.y = y0.y + al.y * S1 + be.y * S2;
            o.z = y0.z + al.z * S1 + be.z * S2;
            o.w = y0.w + al.w * S1 + be.w * S2;
            yseg4[v] = o;
        }
        __syncthreads();   // su/s/carry reused next segment
    }
}

extern "C" void kernel_launch(void* const* d_in, const int* in_sizes, int n_in,
                              void* d_out, int out_size) {
    const float* bco   = (const float*)d_in[0];  // (n_b)
    const float* aco   = (const float*)d_in[1];  // (n_a)
    const float* u     = (const float*)d_in[2];  // (B, T)
    const float* yinit = (const float*)d_in[3];  // (B, 2)
    const float* uinit = (const float*)d_in[4];  // (B, 2)
    float* yout        = (float*)d_out;          // (B, T)

    const int B = in_sizes[3] / 2;               // y_init is (B, 2)
    const int T = in_sizes[2] / B;               // u_in is (B, T)

    iir_shfl_kernel<<<B, NTHREADS>>>(bco, aco, u, yinit, uinit, yout, T);
}

// round 7
// speedup vs baseline: 2.3880x; 1.1380x over previous
#include <cuda_runtime.h>
#include <cstdint>

// Batched 2nd-order IIR via chunked superposition.
//   y[t] = b0*u[t] + b1*u[t-1] - a1*y[t-1] - a2*y[t-2]
// Per segment (SEG=4096): 256 threads x 16-sample chunks.
//   A: cp.async.cg GMEM -> swizzled SMEM (no register round trip)
//   B: zero-state recurrence per chunk (conflict-free float4 LDS), y0 in place
//   C: affine scan of chunk tail-states via warp shuffles (2x2 matrix powers)
//   D: fixup y = y0 + alpha*s1 + beta*s2 fused into coalesced streaming store
//
// Swizzle: chunk c's float4 j lives at float4 index 4c + ((j + (c>>1)) & 3).
// Conflict-free for both chunk-major (B) and coalesced (A/D) access patterns.

#define LCH      16
#define NTHREADS 256
#define SEG      (NTHREADS * LCH)     // 4096
#define CPS      NTHREADS
#define NWARP    (NTHREADS / 32)

__device__ __forceinline__ int swz(int c, int j) {
    return c * 4 + ((j + (c >> 1)) & 3);
}

__global__ __launch_bounds__(NTHREADS, 8)
void iir_ca_kernel(const float* __restrict__ bco,
                   const float* __restrict__ aco,
                   const float* __restrict__ u,
                   const float* __restrict__ yinit,
                   const float* __restrict__ uinit,
                   float* __restrict__ yout,
                   int T)
{
    __shared__ float4 su4[CPS * 4];        // 16 KB swizzled: u, then in-place y0
    __shared__ float4 alpha4[4], beta4[4]; // homogeneous responses (16 each)
    __shared__ float  pw[8][4];            // M^(2^k), row-major 2x2
    __shared__ float4 Ltab[32];            // M^(l+1)
    __shared__ float  agg1[NWARP], agg2[NWARP];
    __shared__ float  q1s[NWARP],  q2s[NWARP];
    __shared__ float  s1[CPS], s2[CPS];    // entering state per chunk
    __shared__ float  carry1, carry2;      // y-state across segments

    const int row  = blockIdx.x;
    const int tid  = threadIdx.x;
    const int lane = tid & 31;
    const int wid  = tid >> 5;

    const float b0 = bco[0], b1 = bco[1];
    const float a1 = aco[0], a2 = aco[1];

    const float* urow = u + (size_t)row * T;
    float*       yrow = yout + (size_t)row * T;

    // ---- One-time tables (tid 0) ----
    if (tid == 0) {
        float* af = (float*)alpha4;
        float* bf = (float*)beta4;
        float p1 = 1.f, p2 = 0.f;   // response to y[-1]=1
        float q1 = 0.f, q2 = 1.f;   // response to y[-2]=1
        #pragma unroll
        for (int t = 0; t < LCH; t++) {
            float pa = -a1 * p1 - a2 * p2;
            float qb = -a1 * q1 - a2 * q2;
            af[t] = pa; bf[t] = qb;
            p2 = p1; p1 = pa;
            q2 = q1; q1 = qb;
        }
        const float M11 = p1, M12 = q1, M21 = p2, M22 = q2;
        float w11 = M11, w12 = M12, w21 = M21, w22 = M22;
        #pragma unroll
        for (int k = 0; k < 8; k++) {
            pw[k][0] = w11; pw[k][1] = w12; pw[k][2] = w21; pw[k][3] = w22;
            float n11 = w11 * w11 + w12 * w21;
            float n12 = w11 * w12 + w12 * w22;
            float n21 = w21 * w11 + w22 * w21;
            float n22 = w21 * w12 + w22 * w22;
            w11 = n11; w12 = n12; w21 = n21; w22 = n22;
        }
        float c11 = M11, c12 = M12, c21 = M21, c22 = M22;
        Ltab[0] = make_float4(c11, c12, c21, c22);
        for (int l = 1; l < 32; l++) {
            float n11 = M11 * c11 + M12 * c21;
            float n12 = M11 * c12 + M12 * c22;
            float n21 = M21 * c11 + M22 * c21;
            float n22 = M21 * c12 + M22 * c22;
            c11 = n11; c12 = n12; c21 = n21; c22 = n22;
            Ltab[l] = make_float4(c11, c12, c21, c22);
        }
        carry1 = yinit[2 * row];
        carry2 = yinit[2 * row + 1];
    }

    const unsigned int sbase = (unsigned int)__cvta_generic_to_shared(su4);
    const int nseg = T / SEG;

    for (int g = 0; g < nseg; g++) {
        const float4* useg4 = (const float4*)(urow + (size_t)g * SEG);

        // ---- Phase A: cp.async GMEM -> swizzled SMEM ----
        #pragma unroll
        for (int k = 0; k < 4; k++) {
            int v = tid + k * NTHREADS;
            unsigned int dst = sbase + (unsigned int)(swz(v >> 2, v & 3) * 16);
            asm volatile("cp.async.cg.shared.global [%0], [%1], 16;\n"
                         :: "r"(dst), "l"(useg4 + v));
        }
        asm volatile("cp.async.commit_group;\n");
        asm volatile("cp.async.wait_group 0;\n");
        __syncthreads();

        // boundary u for each chunk (read BEFORE in-place overwrite)
        float uprev;
        if (tid == 0)
            uprev = (g == 0) ? uinit[2 * row] : __ldg(urow + (size_t)g * SEG - 1);
        else
            uprev = su4[swz(tid - 1, 3)].w;
        __syncthreads();

        // ---- Phase B: zero-state recurrence, y0 in place ----
        float yp1 = 0.f, yp2 = 0.f;
        #pragma unroll
        for (int j = 0; j < 4; j++) {
            int idx = swz(tid, j);
            float4 f = su4[idx];
            float o0 = b0 * f.x + b1 * uprev - a1 * yp1 - a2 * yp2;
            float o1 = b0 * f.y + b1 * f.x   - a1 * o0  - a2 * yp1;
            float o2 = b0 * f.z + b1 * f.y   - a1 * o1  - a2 * o0;
            float o3 = b0 * f.w + b1 * f.z   - a1 * o2  - a2 * o1;
            uprev = f.w; yp1 = o3; yp2 = o2;
            su4[idx] = make_float4(o0, o1, o2, o3);
        }

        // ---- Phase C: affine scan over chunk tail states ----
        float rs1 = yp1, rs2 = yp2;          // d_c
        if (tid == 0) {                       // fold segment entry state into e_0
            float c1 = carry1, c2 = carry2;
            rs1 += pw[0][0] * c1 + pw[0][1] * c2;
            rs2 += pw[0][2] * c1 + pw[0][3] * c2;
            s1[0] = c1; s2[0] = c2;
        }
        #pragma unroll
        for (int k = 0; k < 5; k++) {
            int sh = 1 << k;
            float g1 = __shfl_up_sync(0xffffffffu, rs1, sh);
            float g2 = __shfl_up_sync(0xffffffffu, rs2, sh);
            float m11 = pw[k][0], m12 = pw[k][1];
            float m21 = pw[k][2], m22 = pw[k][3];
            if (lane >= sh) {
                rs1 += m11 * g1 + m12 * g2;
                rs2 += m21 * g1 + m22 * g2;
            }
        }
        if (lane == 31) { agg1[wid] = rs1; agg2[wid] = rs2; }
        __syncthreads();

        if (wid == 0) {                       // scan 8 warp aggregates
            float q1 = 0.f, q2 = 0.f;
            if (lane < NWARP) { q1 = agg1[lane]; q2 = agg2[lane]; }
            #pragma unroll
            for (int k = 0; k < 3; k++) {
                int sh = 1 << k;
                float g1 = __shfl_up_sync(0xffffffffu, q1, sh);
                float g2 = __shfl_up_sync(0xffffffffu, q2, sh);
                float m11 = pw[5 + k][0], m12 = pw[5 + k][1];
                float m21 = pw[5 + k][2], m22 = pw[5 + k][3];
                if (lane >= sh && lane < NWARP) {
                    q1 += m11 * g1 + m12 * g2;
                    q2 += m21 * g1 + m22 * g2;
                }
            }
            if (lane < NWARP) { q1s[lane] = q1; q2s[lane] = q2; }
        }
        __syncthreads();

        if (wid > 0) {                        // splice preceding warps' prefix
            float Q1 = q1s[wid - 1], Q2 = q2s[wid - 1];
            float4 Lm = Ltab[lane];
            rs1 += Lm.x * Q1 + Lm.y * Q2;
            rs2 += Lm.z * Q1 + Lm.w * Q2;
        }
        // rs = state AFTER chunk tid = entering state of chunk tid+1
        if (tid < CPS - 1) { s1[tid + 1] = rs1; s2[tid + 1] = rs2; }
        else               { carry1 = rs1; carry2 = rs2; }
        __syncthreads();

        // ---- Phase D: fixup fused into coalesced streaming store ----
        float4* yseg4 = (float4*)(yrow + (size_t)g * SEG);
        const float4 al = alpha4[tid & 3];   // v&3 == tid&3 for all k
        const float4 be = beta4[tid & 3];
        #pragma unroll
        for (int k = 0; k < 4; k++) {
            int v = tid + k * NTHREADS;
            int c = v >> 2;
            float4 y0 = su4[swz(c, v & 3)];
            float S1 = s1[c], S2 = s2[c];
            float4 o;
            o.x = y0.x + al.x * S1 + be.x * S2;
            o.y = y0.y + al.y * S1 + be.y * S2;
            o.z = y0.z + al.z * S1 + be.z * S2;
            o.w = y0.w + al.w * S1 + be.w * S2;
            __stcs(yseg4 + v, o);
        }
        __syncthreads();   // su/s/carry reused next segment
    }
}

extern "C" void kernel_launch(void* const* d_in, const int* in_sizes, int n_in,
                              void* d_out, int out_size) {
    const float* bco   = (const float*)d_in[0];  // (n_b)
    const float* aco   = (const float*)d_in[1];  // (n_a)
    const float* u     = (const float*)d_in[2];  // (B, T)
    const float* yinit = (const float*)d_in[3];  // (B, 2)
    const float* uinit = (const float*)d_in[4];  // (B, 2)
    float* yout        = (float*)d_out;          // (B, T)

    const int B = in_sizes[3] / 2;               // y_init is (B, 2)
    const int T = in_sizes[2] / B;               // u_in is (B, T)

    iir_ca_kernel<<<B, NTHREADS>>>(bco, aco, u, yinit, uinit, yout, T);
}